// round 13
// baseline (speedup 1.0000x reference)
#include <cuda_runtime.h>
#include <math.h>
#include <stdint.h>

#define R        2048
#define KCLS     20
#define NSC      21
#define IMGW     1333.0f
#define IMGH     800.0f
#define SCORE_TH 0.5f
#define NMS_TH   0.5f
#define TOPK     100
#define KEPT_CAP 192
#define SEL_TGT  160
#define NEG_INF  __int_as_float(0xFF800000)

// ---------------- global scratch (tiny) ----------------
__device__ unsigned long long g_kept[KCLS * TOPK];  // merged keys per class, desc
__device__ int                g_kcnt[KCLS];
__device__ int                g_done = 0;

__device__ __forceinline__ unsigned int fkey(float f) {
    unsigned int u = __float_as_uint(f);
    return (u & 0x80000000u) ? ~u : (u | 0x80000000u);
}
__device__ __forceinline__ float fkey_inv(unsigned int k) {
    unsigned int bits = (k & 0x80000000u) ? (k ^ 0x80000000u) : ~k;
    return __uint_as_float(bits);
}

// ---------------- shared memory layout (dynamic) ----------------
#define OFF_SKEY   0          // u64[2048]   16384
#define OFF_SBOX   16384      // f32[4*2048] 32768
#define OFF_SAREA  49152      // f32[2048]    8192
#define OFF_KEPT   57344      // 5 * f32[192] 3840
#define OFF_FLAGS  61184      // u32[64]       256
#define OFF_DWLO   61440      // u32[64]       256  (also hist scratch)
#define OFF_DWHI   61696      // u32[64]       256
#define OFF_BAD    61952      // u32[64]       256
#define OFF_MISC   62208      // snk,sMerge,sB,sS,sCnt  32
#define OFF_BINS   62240      // u32[1024]    4096
#define OFF_CAND   66336      // u64[512]     4096
#define OFF_MAT    70432      // u32[192*6]   4608  (one-shot NMS bit-matrix)
#define SMEM_BYTES 75040
// merge reuse: sKeys u64[2048]@0, outk u64[100]@16384, scnt int[20]@17184

__device__ __forceinline__ float iou_gt(float x1, float y1, float x2, float y2,
                                        float a, float cx1, float cy1,
                                        float cx2, float cy2, float ca) {
    float xx1 = fmaxf(x1, cx1);
    float yy1 = fmaxf(y1, cy1);
    float xx2 = fminf(x2, cx2);
    float yy2 = fminf(y2, cy2);
    float w = fmaxf(xx2 - xx1, 0.0f);
    float h = fmaxf(yy2 - yy1, 0.0f);
    float inter = w * h;
    float uni = a + ca - inter;
    return inter / fmaxf(uni, 1e-9f);
}

// N-element descending bitonic sort (N in {128,256,512,1024,2048}).
// Threads t < N/2 are active; all 1024 threads must call (block barriers).
template<int N>
__device__ __forceinline__ void bitonicN_desc(unsigned long long* a, int t)
{
    const int H = N >> 1;
    const bool act = (t < H);
    if (act) {
        unsigned long long v0 = a[t], v1 = a[t | H];
        #pragma unroll
        for (unsigned int kk = 2; kk <= 32; kk <<= 1) {
            bool d = ((t & kk) == 0);
            #pragma unroll
            for (unsigned int j = kk >> 1; j >= 1; j >>= 1) {
                unsigned long long o0 = __shfl_xor_sync(0xFFFFFFFFu, v0, j);
                unsigned long long o1 = __shfl_xor_sync(0xFFFFFFFFu, v1, j);
                bool up = ((t & j) == 0);
                v0 = (d == up) ? (v0 > o0 ? v0 : o0) : (v0 < o0 ? v0 : o0);
                v1 = (d == up) ? (v1 > o1 ? v1 : o1) : (v1 < o1 ? v1 : o1);
            }
        }
        a[t] = v0; a[t | H] = v1;
    }
    __syncthreads();

    for (unsigned int kk = 64; kk <= (unsigned int)N; kk <<= 1) {
        unsigned int j = kk >> 1;
        if (kk == (unsigned int)N) {
            if (act) {
                unsigned long long x = a[t], y = a[t | H];
                a[t]     = (x > y) ? x : y;
                a[t | H] = (x > y) ? y : x;
            }
            __syncthreads();
            j = (unsigned int)(H >> 1);
        }
        for (; j >= 32; j >>= 1) {
            if (act) {
                #pragma unroll
                for (int e = 0; e < 2; e++) {
                    unsigned int i = (unsigned int)t + (unsigned int)(e * H);
                    unsigned int ixj = i ^ j;
                    if (ixj > i) {
                        unsigned long long x = a[i], y = a[ixj];
                        bool descBlock = ((i & kk) == 0);
                        if (descBlock ? (x < y) : (x > y)) { a[i] = y; a[ixj] = x; }
                    }
                }
            }
            __syncthreads();
        }
        if (act) {
            unsigned long long v0 = a[t], v1 = a[t | H];
            bool d0 = (((unsigned)t & kk) == 0);
            bool d1 = ((((unsigned)t | (unsigned)H) & kk) == 0);
            #pragma unroll
            for (unsigned int jj = 16; jj >= 1; jj >>= 1) {
                unsigned long long o0 = __shfl_xor_sync(0xFFFFFFFFu, v0, jj);
                unsigned long long o1 = __shfl_xor_sync(0xFFFFFFFFu, v1, jj);
                bool up = (((unsigned)t & jj) == 0);
                v0 = (d0 == up) ? (v0 > o0 ? v0 : o0) : (v0 < o0 ? v0 : o0);
                v1 = (d1 == up) ? (v1 > o1 ? v1 : o1) : (v1 < o1 ? v1 : o1);
            }
            a[t] = v0; a[t | H] = v1;
        }
        __syncthreads();
    }
}

// Given bins[1024], find largest bin B with suffix-count >= target.
__device__ __forceinline__ void hist_select(const unsigned int* bins,
                                            unsigned int* scratch, int t,
                                            int target, int* sB, int* sS)
{
    const int lane = t & 31, w = t >> 5;
    unsigned int v = bins[t];
    #pragma unroll
    for (int d = 1; d < 32; d <<= 1) {
        unsigned int o = __shfl_down_sync(0xFFFFFFFFu, v, d);
        if (lane + d < 32) v += o;
    }
    if (lane == 0) scratch[w] = v;
    __syncthreads();
    if (t < 32) {
        unsigned int wv = scratch[t];
        #pragma unroll
        for (int d = 1; d < 32; d <<= 1) {
            unsigned int o = __shfl_down_sync(0xFFFFFFFFu, wv, d);
            if (t + d < 32) wv += o;
        }
        scratch[32 + t] = wv;
    }
    __syncthreads();
    unsigned int suf  = v + ((w < 31) ? scratch[32 + w + 1] : 0u);
    unsigned int sufn = suf - bins[t];
    if ((int)suf >= target && (int)sufn < target) { *sB = t; *sS = (int)suf; }
    __syncthreads();
}

__global__ void __launch_bounds__(1024, 1)
fused_nms_kernel(const float* __restrict__ boxes,
                 const float* __restrict__ scores,
                 float* __restrict__ out)
{
    extern __shared__ unsigned char smem[];
    unsigned long long* skey = (unsigned long long*)(smem + OFF_SKEY);
    float* sx1   = (float*)(smem + OFF_SBOX);
    float* sy1   = sx1 + R;
    float* sx2   = sy1 + R;
    float* sy2   = sx2 + R;
    float* sarea = (float*)(smem + OFF_SAREA);
    float* kx1   = (float*)(smem + OFF_KEPT);
    float* ky1   = kx1 + KEPT_CAP;
    float* kx2   = ky1 + KEPT_CAP;
    float* ky2   = kx2 + KEPT_CAP;
    float* karea = ky2 + KEPT_CAP;
    unsigned int* sflags  = (unsigned int*)(smem + OFF_FLAGS);
    unsigned int* dwlo    = (unsigned int*)(smem + OFF_DWLO);
    unsigned int* dwhi    = (unsigned int*)(smem + OFF_DWHI);
    unsigned int* sbad    = (unsigned int*)(smem + OFF_BAD);
    unsigned int* bins    = (unsigned int*)(smem + OFF_BINS);
    unsigned long long* cand = (unsigned long long*)(smem + OFF_CAND);
    unsigned int* mat     = (unsigned int*)(smem + OFF_MAT);
    int* snk    = (int*)(smem + OFF_MISC);
    int* sMerge = (int*)(smem + OFF_MISC + 4);
    int* sB     = (int*)(smem + OFF_MISC + 8);
    int* sS     = (int*)(smem + OFF_MISC + 12);
    int* sCnt   = (int*)(smem + OFF_MISC + 16);

    const int c    = blockIdx.x;
    const int t    = threadIdx.x;
    const int lane = t & 31;
    const int wid  = t >> 5;

    if (t < 64) sbad[t] = 0u;
    __syncthreads();

    // ---- phase 1a: vectorized score-finiteness scan (rare-bad bitmap) ----
    {
        const float4* s4 = (const float4*)scores;
        const int n4 = (R * NSC) / 4;
        for (int i = t; i < n4; i += 1024) {
            float4 f = s4[i];
            bool b0 = !isfinite(f.x), b1 = !isfinite(f.y);
            bool b2 = !isfinite(f.z), b3 = !isfinite(f.w);
            if (b0 | b1 | b2 | b3) {
                int e = 4 * i;
                if (b0) { unsigned rr = (unsigned)(e    ) / NSC; atomicOr(&sbad[rr >> 5], 1u << (rr & 31)); }
                if (b1) { unsigned rr = (unsigned)(e + 1) / NSC; atomicOr(&sbad[rr >> 5], 1u << (rr & 31)); }
                if (b2) { unsigned rr = (unsigned)(e + 2) / NSC; atomicOr(&sbad[rr >> 5], 1u << (rr & 31)); }
                if (b3) { unsigned rr = (unsigned)(e + 3) / NSC; atomicOr(&sbad[rr >> 5], 1u << (rr & 31)); }
            }
        }
    }
    __syncthreads();

    // ---- phase 1b: keys (0 for invalid -> sink) + valid count ----
    unsigned long long key0, key1;
    bool v0f, v1f;
    {
        int r0 = t;
        float4 b4 = ((const float4*)boxes)[r0];
        bool fin = isfinite(b4.x) && isfinite(b4.y) && isfinite(b4.z) && isfinite(b4.w);
        fin &= ((sbad[r0 >> 5] >> (r0 & 31)) & 1u) == 0u;
        float s = scores[r0 * NSC + c];
        v0f = fin && (s > SCORE_TH);
        key0 = v0f ? (((unsigned long long)fkey(s) << 32) |
                      (unsigned long long)(0xFFFFFFFFu - (unsigned)r0)) : 0ull;
        skey[r0] = key0;
        int r1 = t + 1024;
        float4 c4 = ((const float4*)boxes)[r1];
        bool fin1 = isfinite(c4.x) && isfinite(c4.y) && isfinite(c4.z) && isfinite(c4.w);
        fin1 &= ((sbad[r1 >> 5] >> (r1 & 31)) & 1u) == 0u;
        float s1 = scores[r1 * NSC + c];
        v1f = fin1 && (s1 > SCORE_TH);
        key1 = v1f ? (((unsigned long long)fkey(s1) << 32) |
                      (unsigned long long)(0xFFFFFFFFu - (unsigned)r1)) : 0ull;
        skey[r1] = key1;
    }
    const int V = __syncthreads_count(v0f) + __syncthreads_count(v1f);

    // ---- phase 2: exact top-S selection (monotone-bin histogram) ----
    bool okb = (key0 == 0ull || (key0 >> 55) == 0x17Eull) &&
               (key1 == 0ull || (key1 >> 55) == 0x17Eull);
    bool selOK = (__syncthreads_and(okb) != 0) && (V > 0);
    int S = 0, B = 1024;
    if (selOK) {
        bins[t] = 0u;
        if (t == 0) { *sB = 1024; *sS = 0; *sCnt = 0; }
        __syncthreads();
        if (key0) atomicAdd(&bins[(unsigned)((key0 >> 45) & 1023)], 1u);
        if (key1) atomicAdd(&bins[(unsigned)((key1 >> 45) & 1023)], 1u);
        __syncthreads();
        int target = (V < SEL_TGT) ? V : SEL_TGT;
        hist_select(bins, dwlo, t, target, sB, sS);
        S = *sS; B = *sB;
        if (S > 0 && S <= 512) {
            if (t < 512) cand[t] = 0ull;
            __syncthreads();
            if (key0 && (int)((key0 >> 45) & 1023) >= B) cand[atomicAdd(sCnt, 1)] = key0;
            if (key1 && (int)((key1 >> 45) & 1023) >= B) cand[atomicAdd(sCnt, 1)] = key1;
            __syncthreads();
            if (S <= 128)      bitonicN_desc<128>(cand, t);
            else if (S <= 256) bitonicN_desc<256>(cand, t);
            else               bitonicN_desc<512>(cand, t);
        } else {
            selOK = false;
        }
    }

    // ---- phases 3+4: gather + NMS (retry with full sort if needed) ----
    int nk = 0;
    for (int attempt = 0; attempt < 2; attempt++) {
        const bool useSel = (attempt == 0) && selOK;
        const unsigned long long* ckey;
        int CV;
        if (useSel) { ckey = cand; CV = S; }
        else { bitonicN_desc<2048>(skey, t); ckey = skey; CV = V; }

        for (int i = t; i < CV; i += 1024) {
            unsigned long long key = ckey[i];
            unsigned int rr = 0xFFFFFFFFu - (unsigned int)(key & 0xFFFFFFFFull);
            float4 b4 = ((const float4*)boxes)[rr];
            float x1 = fminf(fmaxf(b4.x, 0.0f), IMGW);
            float y1 = fminf(fmaxf(b4.y, 0.0f), IMGH);
            float x2 = fminf(fmaxf(b4.z, 0.0f), IMGW);
            float y2 = fminf(fmaxf(b4.w, 0.0f), IMGH);
            sx1[i] = x1; sy1[i] = y1; sx2[i] = x2; sy2[i] = y2;
            sarea[i] = (x2 - x1) * (y2 - y1);
        }
        if (t == 0) *snk = 0;
        __syncthreads();
        nk = 0;

        if (useSel && CV <= KEPT_CAP) {
            // ======= one-shot whole-matrix greedy (fast path) =======
            // build strictly-upper IoU bit-matrix: mat[r*6+cw] bit l
            //   <=> col=cw*32+l > r, col < CV, IoU(r,col) > 0.5
            for (int tid = wid; tid < CV * 6; tid += 32) {
                int r = tid / 6, cw = tid - r * 6;
                int col = (cw << 5) + lane;
                bool bit = false;
                if (col > r && col < CV) {
                    bit = iou_gt(sx1[r], sy1[r], sx2[r], sy2[r], sarea[r],
                                 sx1[col], sy1[col], sx2[col], sy2[col],
                                 sarea[col]) > NMS_TH;
                }
                unsigned int m = __ballot_sync(0xFFFFFFFFu, bit);
                if (lane == 0) mat[tid] = m;
            }
            __syncthreads();

            if (wid == 0) {
                unsigned int pend[6], kept[6];
                #pragma unroll
                for (int g = 0; g < 6; g++) {
                    int lo = g << 5;
                    pend[g] = (CV >= lo + 32) ? 0xFFFFFFFFu
                            : (CV > lo ? ((1u << (CV - lo)) - 1u) : 0u);
                    kept[g] = pend[g];
                }
                // fixed-point greedy over the DAG (converges to exact greedy)
                for (int it = 0; it < KEPT_CAP; it++) {
                    unsigned int contrib[6] = {0u,0u,0u,0u,0u,0u};
                    #pragma unroll
                    for (int g = 0; g < 6; g++) {
                        int r = (g << 5) + lane;
                        if (r < CV && ((kept[g] >> lane) & 1u)) {
                            #pragma unroll
                            for (int w2 = 0; w2 < 6; w2++)
                                contrib[w2] |= mat[r * 6 + w2];
                        }
                    }
                    bool changed = false;
                    #pragma unroll
                    for (int w2 = 0; w2 < 6; w2++) {
                        unsigned int red = __reduce_or_sync(0xFFFFFFFFu, contrib[w2]);
                        unsigned int nw2 = pend[w2] & ~red;
                        changed |= (nw2 != kept[w2]);
                        kept[w2] = nw2;
                    }
                    if (!changed) break;
                }
                // parallel append: rank = popc of kept bits below b
                int base[6]; int total = 0;
                #pragma unroll
                for (int g = 0; g < 6; g++) { base[g] = total; total += __popc(kept[g]); }
                #pragma unroll
                for (int g = 0; g < 6; g++) {
                    int b = (g << 5) + lane;
                    if (b < CV && ((kept[g] >> lane) & 1u)) {
                        int rank = base[g] + __popc(kept[g] & ((1u << lane) - 1u));
                        if (rank < TOPK) {
                            unsigned long long key = ckey[b];
                            unsigned int rr = 0xFFFFFFFFu -
                                (unsigned int)(key & 0xFFFFFFFFull);
                            unsigned int flat = (unsigned)c * R + rr;
                            g_kept[c * TOPK + rank] =
                                (key & 0xFFFFFFFF00000000ull) |
                                (unsigned long long)(0xFFFFFFFFu - flat);
                        }
                    }
                }
                if (lane == 0) *snk = total;
            }
            __syncthreads();
            nk = *snk;
        } else {
            // ======= chunked greedy (fallback path) =======
            const int wcap = (CV + 63) >> 6;
            for (int ch = 0; ch < wcap && nk < TOPK; ch++) {
                #pragma unroll
                for (int half = 0; half < 2; half++) {
                    int cd = (ch << 6) + wid + (half << 5);
                    float x1 = sx1[cd], y1 = sy1[cd];
                    float x2 = sx2[cd], y2 = sy2[cd];
                    float a = sarea[cd];
                    bool loc = false;
                    if (cd < CV) {
                        for (int m = lane; m < nk; m += 32)
                            loc |= (iou_gt(x1, y1, x2, y2, a,
                                           kx1[m], ky1[m], kx2[m], ky2[m], karea[m])
                                    > NMS_TH);
                    }
                    bool sup = __any_sync(0xFFFFFFFFu, loc);
                    if (lane == 0) sflags[wid + (half << 5)] = sup ? 1u : 0u;

                    int c0 = (ch << 6) + lane;
                    int c1 = c0 + 32;
                    bool blo = iou_gt(x1, y1, x2, y2, a,
                                      sx1[c0], sy1[c0], sx2[c0], sy2[c0], sarea[c0]) > NMS_TH;
                    bool bhi = iou_gt(x1, y1, x2, y2, a,
                                      sx1[c1], sy1[c1], sx2[c1], sy2[c1], sarea[c1]) > NMS_TH;
                    unsigned int rlo = __ballot_sync(0xFFFFFFFFu, blo);
                    unsigned int rhi = __ballot_sync(0xFFFFFFFFu, bhi);
                    if (lane == 0) {
                        dwlo[wid + (half << 5)] = rlo;
                        dwhi[wid + (half << 5)] = rhi;
                    }
                }
                __syncthreads();

                if (wid == 0) {
                    unsigned int f0 = sflags[lane], f1 = sflags[32 + lane];
                    unsigned int slo = __ballot_sync(0xFFFFFFFFu, f0 != 0u);
                    unsigned int shi = __ballot_sync(0xFFFFFFFFu, f1 != 0u);
                    unsigned long long suppressed =
                        ((unsigned long long)shi << 32) | (unsigned long long)slo;
                    int rem = CV - (ch << 6);
                    unsigned long long prefix =
                        (rem >= 64) ? ~0ull : ((1ull << rem) - 1ull);
                    unsigned long long pend = prefix & ~suppressed;

                    unsigned long long d0 = (unsigned long long)dwlo[lane] |
                                            ((unsigned long long)dwhi[lane] << 32);
                    unsigned long long d1 = (unsigned long long)dwlo[32 + lane] |
                                            ((unsigned long long)dwhi[32 + lane] << 32);
                    d0 &= (~0ull) << (lane + 1);
                    d1 = (lane == 31) ? 0ull : (d1 & ((~0ull) << (lane + 33)));

                    unsigned long long kept = pend;
                    #pragma unroll 1
                    for (int it = 0; it < 64 && kept; it++) {
                        unsigned long long contrib = 0ull;
                        if ((kept >> lane) & 1ull)        contrib  = d0;
                        if ((kept >> (32 + lane)) & 1ull) contrib |= d1;
                        unsigned int clo = __reduce_or_sync(0xFFFFFFFFu, (unsigned int)contrib);
                        unsigned int chi = __reduce_or_sync(0xFFFFFFFFu, (unsigned int)(contrib >> 32));
                        contrib = ((unsigned long long)chi << 32) | clo;
                        unsigned long long nw = pend & ~contrib;
                        if (nw == kept) break;
                        kept = nw;
                    }

                    int total = __popcll(kept);
                    #pragma unroll
                    for (int hb = 0; hb < 2; hb++) {
                        int b = lane + (hb << 5);
                        if ((kept >> b) & 1ull) {
                            int rankb = __popcll(kept & ((1ull << b) - 1ull));
                            int jj = (ch << 6) + b;
                            int pos = nk + rankb;
                            kx1[pos] = sx1[jj]; ky1[pos] = sy1[jj];
                            kx2[pos] = sx2[jj]; ky2[pos] = sy2[jj];
                            karea[pos] = sarea[jj];
                            if (pos < TOPK) {
                                unsigned long long key = ckey[jj];
                                unsigned int rr = 0xFFFFFFFFu -
                                    (unsigned int)(key & 0xFFFFFFFFull);
                                unsigned int flat = (unsigned)c * R + rr;
                                g_kept[c * TOPK + pos] =
                                    (key & 0xFFFFFFFF00000000ull) |
                                    (unsigned long long)(0xFFFFFFFFu - flat);
                            }
                        }
                    }
                    if (lane == 0) *snk = nk + total;
                }
                __syncthreads();
                nk = *snk;
            }
        }
        if (nk >= TOPK || CV >= V || !useSel) break;
    }

    // ---- completion: last-finishing CTA performs the merge ----
    if (t == 0) {
        g_kcnt[c] = (nk > TOPK) ? TOPK : nk;
        __threadfence();
        int ticket = atomicAdd(&g_done, 1);
        *sMerge = (ticket == KCLS - 1) ? 1 : 0;
        if (*sMerge) g_done = 0;          // reset for next graph replay
    }
    __syncthreads();
    if (*sMerge == 0) return;
    __threadfence();                      // acquire: see all g_kept/g_kcnt

    // ================= merge (single CTA) =================
    unsigned long long* sKeys = (unsigned long long*)(smem + 0);      // [2048]
    unsigned long long* outk  = (unsigned long long*)(smem + 16384);  // [100]
    int* scnt = (int*)(smem + 17184);                                 // [20]
    __syncthreads();

    if (t < KCLS) scnt[t] = g_kcnt[t];
    __syncthreads();

    unsigned long long k0 = 0ull, k1 = 0ull;
    bool q0 = false, q1 = false;
    {
        int i0 = t;
        if (i0 < KCLS * TOPK) {
            int cc = i0 / TOPK, p = i0 % TOPK;
            if (p < scnt[cc]) { k0 = g_kept[i0]; q0 = true; }
        }
        int i1 = t + 1024;
        if (i1 < KCLS * TOPK) {
            int cc = i1 / TOPK, p = i1 % TOPK;
            if (p < scnt[cc]) { k1 = g_kept[i1]; q1 = true; }
        }
    }
    const int stotv = __syncthreads_count(q0) + __syncthreads_count(q1);
    bool mok = (!q0 || (k0 >> 55) == 0x17Eull) &&
               (!q1 || (k1 >> 55) == 0x17Eull);
    bool mSel = (__syncthreads_and(mok) != 0) && (stotv > 0);
    if (mSel) {
        bins[t] = 0u;
        if (t == 0) { *sB = 1024; *sS = 0; *sCnt = 0; }
        __syncthreads();
        if (q0) atomicAdd(&bins[(unsigned)((k0 >> 45) & 1023)], 1u);
        if (q1) atomicAdd(&bins[(unsigned)((k1 >> 45) & 1023)], 1u);
        __syncthreads();
        int target = (stotv < TOPK) ? stotv : TOPK;
        hist_select(bins, dwlo, t, target, sB, sS);
        int MS = *sS, MB = *sB;
        if (MS > 0 && MS <= 512) {
            if (t < 512) cand[t] = 0ull;
            __syncthreads();
            if (q0 && (int)((k0 >> 45) & 1023) >= MB) cand[atomicAdd(sCnt, 1)] = k0;
            if (q1 && (int)((k1 >> 45) & 1023) >= MB) cand[atomicAdd(sCnt, 1)] = k1;
            __syncthreads();
            if (MS <= 128)      bitonicN_desc<128>(cand, t);
            else if (MS <= 256) bitonicN_desc<256>(cand, t);
            else                bitonicN_desc<512>(cand, t);
            if (t < TOPK) outk[t] = cand[t];
            __syncthreads();
        } else {
            mSel = false;
        }
    }
    if (!mSel) {
        sKeys[t] = q0 ? k0 : 0ull;
        sKeys[t + 1024] = q1 ? k1 : 0ull;
        __syncthreads();
        bitonicN_desc<2048>(sKeys, t);
        if (t < TOPK) outk[t] = sKeys[t];
        __syncthreads();
    }

    // degenerate fallback: fewer than TOPK kept -> -inf entries, lowest
    // non-kept flat index first (matches lax.top_k over the masked matrix)
    if (t == 0 && stotv < TOPK) {
        int fill = stotv;
        int flat = 0;
        while (fill < TOPK) {
            int cc = flat >> 11;
            int n = scnt[cc];
            bool is_kept = false;
            for (int q = 0; q < n; q++) {
                unsigned int f2 = 0xFFFFFFFFu -
                    (unsigned int)(g_kept[cc * TOPK + q] & 0xFFFFFFFFull);
                if ((int)f2 == flat) { is_kept = true; break; }
            }
            if (!is_kept) {
                outk[fill] = ((unsigned long long)fkey(NEG_INF) << 32) |
                             (unsigned long long)(0xFFFFFFFFu - (unsigned)flat);
                fill++;
            }
            flat++;
        }
    }
    __syncthreads();

    if (t < TOPK) {
        unsigned long long key = outk[t];
        unsigned int flat = 0xFFFFFFFFu - (unsigned int)(key & 0xFFFFFFFFull);
        float sc = fkey_inv((unsigned int)(key >> 32));
        int cls = (int)(flat >> 11);      // R = 2048 = 2^11
        int rr  = (int)(flat & 2047u);
        float4 b4 = ((const float4*)boxes)[rr];
        out[t] = sc;
        out[TOPK + t * 4 + 0] = fminf(fmaxf(b4.x, 0.0f), IMGW);
        out[TOPK + t * 4 + 1] = fminf(fmaxf(b4.y, 0.0f), IMGH);
        out[TOPK + t * 4 + 2] = fminf(fmaxf(b4.z, 0.0f), IMGW);
        out[TOPK + t * 4 + 3] = fminf(fmaxf(b4.w, 0.0f), IMGH);
        out[TOPK + TOPK * 4 + t]        = (float)cls;
        out[TOPK + TOPK * 4 + TOPK + t] = (float)rr;
    }
}

extern "C" void kernel_launch(void* const* d_in, const int* in_sizes, int n_in,
                              void* d_out, int out_size)
{
    const float* boxes  = (const float*)d_in[0];   // [2048,4]
    const float* scores = (const float*)d_in[1];   // [2048,21]
    float* out = (float*)d_out;

    cudaFuncSetAttribute(fused_nms_kernel,
                         cudaFuncAttributeMaxDynamicSharedMemorySize, SMEM_BYTES);
    fused_nms_kernel<<<KCLS, 1024, SMEM_BYTES>>>(boxes, scores, out);
}

// round 14
// speedup vs baseline: 1.2639x; 1.2639x over previous
#include <cuda_runtime.h>
#include <math.h>
#include <stdint.h>

#define R        2048
#define KCLS     20
#define NSC      21
#define IMGW     1333.0f
#define IMGH     800.0f
#define SCORE_TH 0.5f
#define NMS_TH   0.5f
#define TOPK     100
#define KEPT_CAP 192
#define SEL_TGT  160
#define NEG_INF  __int_as_float(0xFF800000)

// ---------------- global scratch (tiny) ----------------
__device__ unsigned long long g_kept[KCLS * TOPK];  // merged keys per class, desc
__device__ int                g_kcnt[KCLS];
__device__ int                g_done = 0;

__device__ __forceinline__ unsigned int fkey(float f) {
    unsigned int u = __float_as_uint(f);
    return (u & 0x80000000u) ? ~u : (u | 0x80000000u);
}
__device__ __forceinline__ float fkey_inv(unsigned int k) {
    unsigned int bits = (k & 0x80000000u) ? (k ^ 0x80000000u) : ~k;
    return __uint_as_float(bits);
}

// ---------------- shared memory layout (dynamic) ----------------
#define OFF_SKEY   0          // u64[2048]   16384
#define OFF_SBOX   16384      // f32[4*2048] 32768
#define OFF_SAREA  49152      // f32[2048]    8192
#define OFF_KEPT   57344      // 5 * f32[192] 3840
#define OFF_FLAGS  61184      // u32[64]       256
#define OFF_DWLO   61440      // u32[64]       256  (also hist scratch)
#define OFF_DWHI   61696      // u32[64]       256
#define OFF_BAD    61952      // u32[64]       256
#define OFF_MISC   62208      // snk,sMerge,sB,sS,sCnt,sVcnt,sOK  32
#define OFF_BINS   62240      // u32[1024]    4096
#define OFF_CAND   66336      // u64[512]     4096
#define SMEM_BYTES 70432
// merge reuse: sKeys u64[2048]@0, outk u64[100]@16384, scnt int[20]@17184

__device__ __forceinline__ float iou_gt(float x1, float y1, float x2, float y2,
                                        float a, float cx1, float cy1,
                                        float cx2, float cy2, float ca) {
    float xx1 = fmaxf(x1, cx1);
    float yy1 = fmaxf(y1, cy1);
    float xx2 = fminf(x2, cx2);
    float yy2 = fminf(y2, cy2);
    float w = fmaxf(xx2 - xx1, 0.0f);
    float h = fmaxf(yy2 - yy1, 0.0f);
    float inter = w * h;
    float uni = a + ca - inter;
    return inter / fmaxf(uni, 1e-9f);
}

// N-element descending bitonic sort (N in {128,256,512,1024,2048}).
// Threads t < N/2 are active; all 1024 threads must call (block barriers).
template<int N>
__device__ __forceinline__ void bitonicN_desc(unsigned long long* a, int t)
{
    const int H = N >> 1;
    const bool act = (t < H);
    if (act) {
        unsigned long long v0 = a[t], v1 = a[t | H];
        #pragma unroll
        for (unsigned int kk = 2; kk <= 32; kk <<= 1) {
            bool d = ((t & kk) == 0);
            #pragma unroll
            for (unsigned int j = kk >> 1; j >= 1; j >>= 1) {
                unsigned long long o0 = __shfl_xor_sync(0xFFFFFFFFu, v0, j);
                unsigned long long o1 = __shfl_xor_sync(0xFFFFFFFFu, v1, j);
                bool up = ((t & j) == 0);
                v0 = (d == up) ? (v0 > o0 ? v0 : o0) : (v0 < o0 ? v0 : o0);
                v1 = (d == up) ? (v1 > o1 ? v1 : o1) : (v1 < o1 ? v1 : o1);
            }
        }
        a[t] = v0; a[t | H] = v1;
    }
    __syncthreads();

    for (unsigned int kk = 64; kk <= (unsigned int)N; kk <<= 1) {
        unsigned int j = kk >> 1;
        if (kk == (unsigned int)N) {
            if (act) {
                unsigned long long x = a[t], y = a[t | H];
                a[t]     = (x > y) ? x : y;
                a[t | H] = (x > y) ? y : x;
            }
            __syncthreads();
            j = (unsigned int)(H >> 1);
        }
        for (; j >= 32; j >>= 1) {
            if (act) {
                #pragma unroll
                for (int e = 0; e < 2; e++) {
                    unsigned int i = (unsigned int)t + (unsigned int)(e * H);
                    unsigned int ixj = i ^ j;
                    if (ixj > i) {
                        unsigned long long x = a[i], y = a[ixj];
                        bool descBlock = ((i & kk) == 0);
                        if (descBlock ? (x < y) : (x > y)) { a[i] = y; a[ixj] = x; }
                    }
                }
            }
            __syncthreads();
        }
        if (act) {
            unsigned long long v0 = a[t], v1 = a[t | H];
            bool d0 = (((unsigned)t & kk) == 0);
            bool d1 = ((((unsigned)t | (unsigned)H) & kk) == 0);
            #pragma unroll
            for (unsigned int jj = 16; jj >= 1; jj >>= 1) {
                unsigned long long o0 = __shfl_xor_sync(0xFFFFFFFFu, v0, jj);
                unsigned long long o1 = __shfl_xor_sync(0xFFFFFFFFu, v1, jj);
                bool up = (((unsigned)t & jj) == 0);
                v0 = (d0 == up) ? (v0 > o0 ? v0 : o0) : (v0 < o0 ? v0 : o0);
                v1 = (d1 == up) ? (v1 > o1 ? v1 : o1) : (v1 < o1 ? v1 : o1);
            }
            a[t] = v0; a[t | H] = v1;
        }
        __syncthreads();
    }
}

// Given bins[1024], find largest bin B with suffix-count >= target.
__device__ __forceinline__ void hist_select(const unsigned int* bins,
                                            unsigned int* scratch, int t,
                                            int target, int* sB, int* sS)
{
    const int lane = t & 31, w = t >> 5;
    unsigned int v = bins[t];
    #pragma unroll
    for (int d = 1; d < 32; d <<= 1) {
        unsigned int o = __shfl_down_sync(0xFFFFFFFFu, v, d);
        if (lane + d < 32) v += o;
    }
    if (lane == 0) scratch[w] = v;
    __syncthreads();
    if (t < 32) {
        unsigned int wv = scratch[t];
        #pragma unroll
        for (int d = 1; d < 32; d <<= 1) {
            unsigned int o = __shfl_down_sync(0xFFFFFFFFu, wv, d);
            if (t + d < 32) wv += o;
        }
        scratch[32 + t] = wv;
    }
    __syncthreads();
    unsigned int suf  = v + ((w < 31) ? scratch[32 + w + 1] : 0u);
    unsigned int sufn = suf - bins[t];
    if ((int)suf >= target && (int)sufn < target) { *sB = t; *sS = (int)suf; }
    __syncthreads();
}

__global__ void __launch_bounds__(1024, 1)
fused_nms_kernel(const float* __restrict__ boxes,
                 const float* __restrict__ scores,
                 float* __restrict__ out)
{
    extern __shared__ unsigned char smem[];
    unsigned long long* skey = (unsigned long long*)(smem + OFF_SKEY);
    float* sx1   = (float*)(smem + OFF_SBOX);
    float* sy1   = sx1 + R;
    float* sx2   = sy1 + R;
    float* sy2   = sx2 + R;
    float* sarea = (float*)(smem + OFF_SAREA);
    float* kx1   = (float*)(smem + OFF_KEPT);
    float* ky1   = kx1 + KEPT_CAP;
    float* kx2   = ky1 + KEPT_CAP;
    float* ky2   = kx2 + KEPT_CAP;
    float* karea = ky2 + KEPT_CAP;
    unsigned int* sflags  = (unsigned int*)(smem + OFF_FLAGS);
    unsigned int* dwlo    = (unsigned int*)(smem + OFF_DWLO);
    unsigned int* dwhi    = (unsigned int*)(smem + OFF_DWHI);
    unsigned int* sbad    = (unsigned int*)(smem + OFF_BAD);
    unsigned int* bins    = (unsigned int*)(smem + OFF_BINS);
    unsigned long long* cand = (unsigned long long*)(smem + OFF_CAND);
    int* snk    = (int*)(smem + OFF_MISC);
    int* sMerge = (int*)(smem + OFF_MISC + 4);
    int* sB     = (int*)(smem + OFF_MISC + 8);
    int* sS     = (int*)(smem + OFF_MISC + 12);
    int* sCnt   = (int*)(smem + OFF_MISC + 16);
    int* sVcnt  = (int*)(smem + OFF_MISC + 20);
    int* sOK    = (int*)(smem + OFF_MISC + 24);

    const int c    = blockIdx.x;
    const int t    = threadIdx.x;
    const int lane = t & 31;
    const int wid  = t >> 5;

    if (t < 64) sbad[t] = 0u;
    if (t == 64) { *sVcnt = 0; *sOK = 1; }
    __syncthreads();

    // ---- phase 1a: vectorized score-finiteness scan (rare-bad bitmap) ----
    {
        const float4* s4 = (const float4*)scores;
        const int n4 = (R * NSC) / 4;
        for (int i = t; i < n4; i += 1024) {
            float4 f = s4[i];
            bool b0 = !isfinite(f.x), b1 = !isfinite(f.y);
            bool b2 = !isfinite(f.z), b3 = !isfinite(f.w);
            if (b0 | b1 | b2 | b3) {
                int e = 4 * i;
                if (b0) { unsigned rr = (unsigned)(e    ) / NSC; atomicOr(&sbad[rr >> 5], 1u << (rr & 31)); }
                if (b1) { unsigned rr = (unsigned)(e + 1) / NSC; atomicOr(&sbad[rr >> 5], 1u << (rr & 31)); }
                if (b2) { unsigned rr = (unsigned)(e + 2) / NSC; atomicOr(&sbad[rr >> 5], 1u << (rr & 31)); }
                if (b3) { unsigned rr = (unsigned)(e + 3) / NSC; atomicOr(&sbad[rr >> 5], 1u << (rr & 31)); }
            }
        }
    }
    __syncthreads();

    // ---- phase 1b: keys (0 for invalid -> sink) + valid count (1 barrier) ----
    unsigned long long key0, key1;
    bool v0f, v1f;
    {
        int r0 = t;
        float4 b4 = ((const float4*)boxes)[r0];
        bool fin = isfinite(b4.x) && isfinite(b4.y) && isfinite(b4.z) && isfinite(b4.w);
        fin &= ((sbad[r0 >> 5] >> (r0 & 31)) & 1u) == 0u;
        float s = scores[r0 * NSC + c];
        v0f = fin && (s > SCORE_TH);
        key0 = v0f ? (((unsigned long long)fkey(s) << 32) |
                      (unsigned long long)(0xFFFFFFFFu - (unsigned)r0)) : 0ull;
        skey[r0] = key0;
        int r1 = t + 1024;
        float4 c4 = ((const float4*)boxes)[r1];
        bool fin1 = isfinite(c4.x) && isfinite(c4.y) && isfinite(c4.z) && isfinite(c4.w);
        fin1 &= ((sbad[r1 >> 5] >> (r1 & 31)) & 1u) == 0u;
        float s1 = scores[r1 * NSC + c];
        v1f = fin1 && (s1 > SCORE_TH);
        key1 = v1f ? (((unsigned long long)fkey(s1) << 32) |
                      (unsigned long long)(0xFFFFFFFFu - (unsigned)r1)) : 0ull;
        skey[r1] = key1;
    }
    {
        bool okb = (key0 == 0ull || (key0 >> 55) == 0x17Eull) &&
                   (key1 == 0ull || (key1 >> 55) == 0x17Eull);
        unsigned int bv0 = __ballot_sync(0xFFFFFFFFu, v0f);
        unsigned int bv1 = __ballot_sync(0xFFFFFFFFu, v1f);
        unsigned int bok = __ballot_sync(0xFFFFFFFFu, okb);
        if (lane == 0) {
            int add = __popc(bv0) + __popc(bv1);
            if (add) atomicAdd(sVcnt, add);
            if (bok != 0xFFFFFFFFu) atomicAnd(sOK, 0);
        }
    }
    __syncthreads();
    const int V = *sVcnt;

    // ---- phase 2: exact top-S selection (monotone-bin histogram) ----
    bool selOK = (*sOK != 0) && (V > 0);
    int S = 0, B = 1024;
    if (selOK) {
        bins[t] = 0u;
        if (t == 0) { *sB = 1024; *sS = 0; *sCnt = 0; }
        __syncthreads();
        if (key0) atomicAdd(&bins[(unsigned)((key0 >> 45) & 1023)], 1u);
        if (key1) atomicAdd(&bins[(unsigned)((key1 >> 45) & 1023)], 1u);
        __syncthreads();
        int target = (V < SEL_TGT) ? V : SEL_TGT;
        hist_select(bins, dwlo, t, target, sB, sS);
        S = *sS; B = *sB;
        if (S > 0 && S <= 512) {
            if (t < 512) cand[t] = 0ull;
            __syncthreads();
            if (key0 && (int)((key0 >> 45) & 1023) >= B) cand[atomicAdd(sCnt, 1)] = key0;
            if (key1 && (int)((key1 >> 45) & 1023) >= B) cand[atomicAdd(sCnt, 1)] = key1;
            __syncthreads();
            if (S <= 128)      bitonicN_desc<128>(cand, t);
            else if (S <= 256) bitonicN_desc<256>(cand, t);
            else               bitonicN_desc<512>(cand, t);
        } else {
            selOK = false;
        }
    }

    // ---- phases 3+4: gather + chunked NMS (retry with full sort if needed) ----
    int nk = 0;
    for (int attempt = 0; attempt < 2; attempt++) {
        const bool useSel = (attempt == 0) && selOK;
        const unsigned long long* ckey;
        int CV;
        if (useSel) { ckey = cand; CV = S; }
        else { bitonicN_desc<2048>(skey, t); ckey = skey; CV = V; }

        for (int i = t; i < CV; i += 1024) {
            unsigned long long key = ckey[i];
            unsigned int rr = 0xFFFFFFFFu - (unsigned int)(key & 0xFFFFFFFFull);
            float4 b4 = ((const float4*)boxes)[rr];
            float x1 = fminf(fmaxf(b4.x, 0.0f), IMGW);
            float y1 = fminf(fmaxf(b4.y, 0.0f), IMGH);
            float x2 = fminf(fmaxf(b4.z, 0.0f), IMGW);
            float y2 = fminf(fmaxf(b4.w, 0.0f), IMGH);
            sx1[i] = x1; sy1[i] = y1; sx2[i] = x2; sy2[i] = y2;
            sarea[i] = (x2 - x1) * (y2 - y1);
        }
        if (t == 0) *snk = 0;
        __syncthreads();
        nk = 0;

        const int wcap = (CV + 63) >> 6;
        for (int ch = 0; ch < wcap && nk < TOPK; ch++) {
            #pragma unroll
            for (int half = 0; half < 2; half++) {
                int cd = (ch << 6) + wid + (half << 5);
                float x1 = sx1[cd], y1 = sy1[cd];
                float x2 = sx2[cd], y2 = sy2[cd];
                float a = sarea[cd];
                bool loc = false;
                if (cd < CV) {
                    for (int m = lane; m < nk; m += 32)
                        loc |= (iou_gt(x1, y1, x2, y2, a,
                                       kx1[m], ky1[m], kx2[m], ky2[m], karea[m])
                                > NMS_TH);
                }
                bool sup = __any_sync(0xFFFFFFFFu, loc);
                if (lane == 0) sflags[wid + (half << 5)] = sup ? 1u : 0u;

                int c0 = (ch << 6) + lane;
                int c1 = c0 + 32;
                bool blo = iou_gt(x1, y1, x2, y2, a,
                                  sx1[c0], sy1[c0], sx2[c0], sy2[c0], sarea[c0]) > NMS_TH;
                bool bhi = iou_gt(x1, y1, x2, y2, a,
                                  sx1[c1], sy1[c1], sx2[c1], sy2[c1], sarea[c1]) > NMS_TH;
                unsigned int rlo = __ballot_sync(0xFFFFFFFFu, blo);
                unsigned int rhi = __ballot_sync(0xFFFFFFFFu, bhi);
                if (lane == 0) {
                    dwlo[wid + (half << 5)] = rlo;
                    dwhi[wid + (half << 5)] = rhi;
                }
            }
            __syncthreads();

            if (wid == 0) {
                unsigned int f0 = sflags[lane], f1 = sflags[32 + lane];
                unsigned int slo = __ballot_sync(0xFFFFFFFFu, f0 != 0u);
                unsigned int shi = __ballot_sync(0xFFFFFFFFu, f1 != 0u);
                unsigned long long suppressed =
                    ((unsigned long long)shi << 32) | (unsigned long long)slo;
                int rem = CV - (ch << 6);
                unsigned long long prefix =
                    (rem >= 64) ? ~0ull : ((1ull << rem) - 1ull);
                unsigned long long pend = prefix & ~suppressed;

                // diagonal rows, masked to strictly-higher bits (DAG)
                unsigned long long d0 = (unsigned long long)dwlo[lane] |
                                        ((unsigned long long)dwhi[lane] << 32);
                unsigned long long d1 = (unsigned long long)dwlo[32 + lane] |
                                        ((unsigned long long)dwhi[32 + lane] << 32);
                d0 &= (~0ull) << (lane + 1);                      // row = lane (<=31)
                d1 = (lane == 31) ? 0ull : (d1 & ((~0ull) << (lane + 33)));

                // fixed-point parallel greedy (converges <= DAG depth + 1)
                unsigned long long kept = pend;
                #pragma unroll 1
                for (int it = 0; it < 64 && kept; it++) {
                    unsigned long long contrib = 0ull;
                    if ((kept >> lane) & 1ull)        contrib  = d0;
                    if ((kept >> (32 + lane)) & 1ull) contrib |= d1;
                    unsigned int clo = __reduce_or_sync(0xFFFFFFFFu, (unsigned int)contrib);
                    unsigned int chi = __reduce_or_sync(0xFFFFFFFFu, (unsigned int)(contrib >> 32));
                    contrib = ((unsigned long long)chi << 32) | clo;
                    unsigned long long nw = pend & ~contrib;
                    if (nw == kept) break;
                    kept = nw;
                }

                // parallel append: slot = popc of kept bits below b
                int total = __popcll(kept);
                #pragma unroll
                for (int hb = 0; hb < 2; hb++) {
                    int b = lane + (hb << 5);
                    if ((kept >> b) & 1ull) {
                        int rankb = __popcll(kept & ((1ull << b) - 1ull));
                        int jj = (ch << 6) + b;
                        int pos = nk + rankb;
                        kx1[pos] = sx1[jj]; ky1[pos] = sy1[jj];
                        kx2[pos] = sx2[jj]; ky2[pos] = sy2[jj];
                        karea[pos] = sarea[jj];
                        if (pos < TOPK) {
                            unsigned long long key = ckey[jj];
                            unsigned int rr = 0xFFFFFFFFu -
                                (unsigned int)(key & 0xFFFFFFFFull);
                            unsigned int flat = (unsigned)c * R + rr;
                            g_kept[c * TOPK + pos] =
                                (key & 0xFFFFFFFF00000000ull) |
                                (unsigned long long)(0xFFFFFFFFu - flat);
                        }
                    }
                }
                if (lane == 0) *snk = nk + total;
            }
            __syncthreads();
            nk = *snk;
        }
        if (nk >= TOPK || CV >= V || !useSel) break;
    }

    // ---- completion: last-finishing CTA performs the merge ----
    if (t == 0) {
        g_kcnt[c] = (nk > TOPK) ? TOPK : nk;
        __threadfence();
        int ticket = atomicAdd(&g_done, 1);
        *sMerge = (ticket == KCLS - 1) ? 1 : 0;
        if (*sMerge) g_done = 0;          // reset for next graph replay
    }
    __syncthreads();
    if (*sMerge == 0) return;
    __threadfence();                      // acquire: see all g_kept/g_kcnt

    // ================= merge (single CTA) =================
    unsigned long long* sKeys = (unsigned long long*)(smem + 0);      // [2048]
    unsigned long long* outk  = (unsigned long long*)(smem + 16384);  // [100]
    int* scnt = (int*)(smem + 17184);                                 // [20]
    __syncthreads();

    if (t < KCLS) scnt[t] = g_kcnt[t];
    if (t == 64) { *sVcnt = 0; *sOK = 1; }
    __syncthreads();

    unsigned long long k0 = 0ull, k1 = 0ull;
    bool q0 = false, q1 = false;
    {
        int i0 = t;
        if (i0 < KCLS * TOPK) {
            int cc = i0 / TOPK, p = i0 % TOPK;
            if (p < scnt[cc]) { k0 = g_kept[i0]; q0 = true; }
        }
        int i1 = t + 1024;
        if (i1 < KCLS * TOPK) {
            int cc = i1 / TOPK, p = i1 % TOPK;
            if (p < scnt[cc]) { k1 = g_kept[i1]; q1 = true; }
        }
    }
    {
        bool mok = (!q0 || (k0 >> 55) == 0x17Eull) &&
                   (!q1 || (k1 >> 55) == 0x17Eull);
        unsigned int bq0 = __ballot_sync(0xFFFFFFFFu, q0);
        unsigned int bq1 = __ballot_sync(0xFFFFFFFFu, q1);
        unsigned int bmk = __ballot_sync(0xFFFFFFFFu, mok);
        if (lane == 0) {
            int add = __popc(bq0) + __popc(bq1);
            if (add) atomicAdd(sVcnt, add);
            if (bmk != 0xFFFFFFFFu) atomicAnd(sOK, 0);
        }
    }
    __syncthreads();
    const int stotv = *sVcnt;
    bool mSel = (*sOK != 0) && (stotv > 0);
    if (mSel) {
        bins[t] = 0u;
        if (t == 0) { *sB = 1024; *sS = 0; *sCnt = 0; }
        __syncthreads();
        if (q0) atomicAdd(&bins[(unsigned)((k0 >> 45) & 1023)], 1u);
        if (q1) atomicAdd(&bins[(unsigned)((k1 >> 45) & 1023)], 1u);
        __syncthreads();
        int target = (stotv < TOPK) ? stotv : TOPK;
        hist_select(bins, dwlo, t, target, sB, sS);
        int MS = *sS, MB = *sB;
        if (MS > 0 && MS <= 512) {
            if (t < 512) cand[t] = 0ull;
            __syncthreads();
            if (q0 && (int)((k0 >> 45) & 1023) >= MB) cand[atomicAdd(sCnt, 1)] = k0;
            if (q1 && (int)((k1 >> 45) & 1023) >= MB) cand[atomicAdd(sCnt, 1)] = k1;
            __syncthreads();
            if (MS <= 128)      bitonicN_desc<128>(cand, t);
            else if (MS <= 256) bitonicN_desc<256>(cand, t);
            else                bitonicN_desc<512>(cand, t);
            if (t < TOPK) outk[t] = cand[t];
            __syncthreads();
        } else {
            mSel = false;
        }
    }
    if (!mSel) {
        sKeys[t] = q0 ? k0 : 0ull;
        sKeys[t + 1024] = q1 ? k1 : 0ull;
        __syncthreads();
        bitonicN_desc<2048>(sKeys, t);
        if (t < TOPK) outk[t] = sKeys[t];
        __syncthreads();
    }

    // degenerate fallback: fewer than TOPK kept -> -inf entries, lowest
    // non-kept flat index first (matches lax.top_k over the masked matrix)
    if (t == 0 && stotv < TOPK) {
        int fill = stotv;
        int flat = 0;
        while (fill < TOPK) {
            int cc = flat >> 11;
            int n = scnt[cc];
            bool is_kept = false;
            for (int q = 0; q < n; q++) {
                unsigned int f2 = 0xFFFFFFFFu -
                    (unsigned int)(g_kept[cc * TOPK + q] & 0xFFFFFFFFull);
                if ((int)f2 == flat) { is_kept = true; break; }
            }
            if (!is_kept) {
                outk[fill] = ((unsigned long long)fkey(NEG_INF) << 32) |
                             (unsigned long long)(0xFFFFFFFFu - (unsigned)flat);
                fill++;
            }
            flat++;
        }
    }
    __syncthreads();

    if (t < TOPK) {
        unsigned long long key = outk[t];
        unsigned int flat = 0xFFFFFFFFu - (unsigned int)(key & 0xFFFFFFFFull);
        float sc = fkey_inv((unsigned int)(key >> 32));
        int cls = (int)(flat >> 11);      // R = 2048 = 2^11
        int rr  = (int)(flat & 2047u);
        float4 b4 = ((const float4*)boxes)[rr];
        out[t] = sc;
        out[TOPK + t * 4 + 0] = fminf(fmaxf(b4.x, 0.0f), IMGW);
        out[TOPK + t * 4 + 1] = fminf(fmaxf(b4.y, 0.0f), IMGH);
        out[TOPK + t * 4 + 2] = fminf(fmaxf(b4.z, 0.0f), IMGW);
        out[TOPK + t * 4 + 3] = fminf(fmaxf(b4.w, 0.0f), IMGH);
        out[TOPK + TOPK * 4 + t]        = (float)cls;
        out[TOPK + TOPK * 4 + TOPK + t] = (float)rr;
    }
}

extern "C" void kernel_launch(void* const* d_in, const int* in_sizes, int n_in,
                              void* d_out, int out_size)
{
    const float* boxes  = (const float*)d_in[0];   // [2048,4]
    const float* scores = (const float*)d_in[1];   // [2048,21]
    float* out = (float*)d_out;

    cudaFuncSetAttribute(fused_nms_kernel,
                         cudaFuncAttributeMaxDynamicSharedMemorySize, SMEM_BYTES);
    fused_nms_kernel<<<KCLS, 1024, SMEM_BYTES>>>(boxes, scores, out);
}